// round 3
// baseline (speedup 1.0000x reference)
#include <cuda_runtime.h>
#include <math.h>

// Problem constants
constexpr int NB = 64;    // batch
constexpr int NT = 256;   // time
constexpr int ND = 256;   // embed dim
constexpr int NH = 256;   // hidden per direction
constexpr int NC = 32;    // tags
constexpr int NG = 1024;  // 4*NH gate rows

// Scratch (static device allocations; no cudaMalloc allowed)
__device__ __align__(16) float g_gates[(size_t)2 * NB * NT * NG]; // 128 MB: input-projected gate preacts per dir
__device__ __align__(16) float g_h[(size_t)2 * NB * NT * NH];     // 32 MB: LSTM outputs per dir (bwd in reversed time)
__device__ __align__(16) float g_em[(size_t)NB * NT * NC];        // emissions
__device__ int g_hist[(size_t)NT * NB * NC];                      // viterbi backpointers

__device__ __forceinline__ float sigf(float x) { return 1.0f / (1.0f + __expf(-x)); }

// ---------------------------------------------------------------------------
// Kernel 1: embedding gather + input projection for both directions.
// gates[dir][b][t][g] = dot(emb[token(dir,b,t)], w_ih[g,:]) + b_ih[g] + b_hh[g]
// token: fwd = sentences[b][t]; bwd = sentences[b][rev(b,t)]
// SGEMM: BM=128, BN=128, BK=16, 256 threads, 8x8 per-thread microtile.
// ---------------------------------------------------------------------------
__global__ void __launch_bounds__(256) input_proj_kernel(
    const int* __restrict__ sent, const int* __restrict__ lens,
    const float* __restrict__ emb,
    const float* __restrict__ w_f, const float* __restrict__ bi_f, const float* __restrict__ bh_f,
    const float* __restrict__ w_b, const float* __restrict__ bi_b, const float* __restrict__ bh_b)
{
    const int dir = blockIdx.y >> 3;
    const int n0  = (blockIdx.y & 7) * 128;
    const int m0  = blockIdx.x * 128;

    const float* __restrict__ W  = dir ? w_b  : w_f;
    const float* __restrict__ BI = dir ? bi_b : bi_f;
    const float* __restrict__ BH = dir ? bh_b : bh_f;

    __shared__ __align__(16) float As[16][128];
    __shared__ __align__(16) float Bs[16][128];
    __shared__ int toks[128];

    const int tid = threadIdx.x;
    if (tid < 128) {
        int m = m0 + tid;
        int b = m >> 8, t = m & 255;
        int ts = t;
        if (dir) { int len = lens[b]; if (t < len) ts = len - 1 - t; }
        toks[tid] = sent[b * NT + ts];
    }
    __syncthreads();

    const int lrow = tid >> 1;   // 0..127
    const int lcol = tid & 1;    // 0..1
    const int tx = tid & 15, ty = tid >> 4;

    float acc[8][8];
#pragma unroll
    for (int i = 0; i < 8; i++)
#pragma unroll
        for (int j = 0; j < 8; j++) acc[i][j] = 0.0f;

    const float* arow = emb + (size_t)toks[lrow] * ND;
    const float* brow = W + (size_t)(n0 + lrow) * ND;

    for (int kk = 0; kk < ND; kk += 16) {
#pragma unroll
        for (int it = 0; it < 2; ++it) {
            int g4 = lcol + 2 * it;  // covers float4 groups 0..3 of the 16-wide k tile
            float4 av = *(const float4*)(arow + kk + g4 * 4);
            float4 bv = *(const float4*)(brow + kk + g4 * 4);
            As[g4 * 4 + 0][lrow] = av.x; As[g4 * 4 + 1][lrow] = av.y;
            As[g4 * 4 + 2][lrow] = av.z; As[g4 * 4 + 3][lrow] = av.w;
            Bs[g4 * 4 + 0][lrow] = bv.x; Bs[g4 * 4 + 1][lrow] = bv.y;
            Bs[g4 * 4 + 2][lrow] = bv.z; Bs[g4 * 4 + 3][lrow] = bv.w;
        }
        __syncthreads();
#pragma unroll
        for (int k = 0; k < 16; ++k) {
            float4 a0 = *(const float4*)&As[k][ty * 8];
            float4 a1 = *(const float4*)&As[k][ty * 8 + 4];
            float4 b0 = *(const float4*)&Bs[k][tx * 8];
            float4 b1 = *(const float4*)&Bs[k][tx * 8 + 4];
            float a[8] = {a0.x, a0.y, a0.z, a0.w, a1.x, a1.y, a1.z, a1.w};
            float bb[8] = {b0.x, b0.y, b0.z, b0.w, b1.x, b1.y, b1.z, b1.w};
#pragma unroll
            for (int i = 0; i < 8; i++)
#pragma unroll
                for (int j = 0; j < 8; j++) acc[i][j] = fmaf(a[i], bb[j], acc[i][j]);
        }
        __syncthreads();
    }

    float bias[8];
#pragma unroll
    for (int j = 0; j < 8; j++) {
        int n = n0 + tx * 8 + j;
        bias[j] = BI[n] + BH[n];
    }
#pragma unroll
    for (int i = 0; i < 8; i++) {
        int m = m0 + ty * 8 + i;
        float* o = g_gates + ((size_t)dir * (NB * NT) + m) * NG + n0 + tx * 8;
#pragma unroll
        for (int j = 0; j < 8; j++) o[j] = acc[i][j] + bias[j];
    }
}

// ---------------------------------------------------------------------------
// Kernel 2: recurrent LSTM. Grid = 64 blocks: blockIdx&1 = direction,
// blockIdx>>1 = batch pair (2 batch elements per block to amortize w_hh reads).
// 1024 threads: thread = gate row g; dot over hidden with smem-resident h.
// ---------------------------------------------------------------------------
__global__ void __launch_bounds__(1024, 1) lstm_kernel(
    const float* __restrict__ w_hh_f, const float* __restrict__ w_hh_b)
{
    const int dir = blockIdx.x & 1;
    const int b0 = (blockIdx.x >> 1) * 2;
    const float* __restrict__ whh = dir ? w_hh_b : w_hh_f;

    __shared__ __align__(16) float hs[2][NH];
    __shared__ float cs[2][NH];
    __shared__ float gs[2][NG];

    const int tid = threadIdx.x;
    if (tid < 2 * NH) {
        hs[tid >> 8][tid & 255] = 0.0f;
        cs[tid >> 8][tid & 255] = 0.0f;
    }
    __syncthreads();

    const float4* wrow = (const float4*)(whh + (size_t)tid * NH);
    const float* gin0 = g_gates + ((size_t)dir * NB + b0) * NT * NG;
    const float* gin1 = gin0 + (size_t)NT * NG;
    float* hout0 = g_h + ((size_t)dir * NB + b0) * NT * NH;
    float* hout1 = hout0 + (size_t)NT * NH;
    const float4* h0v = (const float4*)hs[0];
    const float4* h1v = (const float4*)hs[1];

    for (int t = 0; t < NT; ++t) {
        float acc0 = gin0[t * NG + tid];
        float acc1 = gin1[t * NG + tid];
#pragma unroll 4
        for (int k = 0; k < NH / 4; ++k) {
            float4 w4 = wrow[k];
            float4 a = h0v[k];
            float4 b = h1v[k];
            acc0 = fmaf(w4.x, a.x, acc0); acc0 = fmaf(w4.y, a.y, acc0);
            acc0 = fmaf(w4.z, a.z, acc0); acc0 = fmaf(w4.w, a.w, acc0);
            acc1 = fmaf(w4.x, b.x, acc1); acc1 = fmaf(w4.y, b.y, acc1);
            acc1 = fmaf(w4.z, b.z, acc1); acc1 = fmaf(w4.w, b.w, acc1);
        }
        gs[0][tid] = acc0;
        gs[1][tid] = acc1;
        __syncthreads();
        if (tid < 2 * NH) {
            int bb = tid >> 8, j = tid & 255;
            float iv = sigf(gs[bb][j]);
            float fv = sigf(gs[bb][256 + j]);
            float gv = tanhf(gs[bb][512 + j]);
            float ov = sigf(gs[bb][768 + j]);
            float c = fv * cs[bb][j] + iv * gv;
            float h = ov * tanhf(c);
            cs[bb][j] = c;
            hs[bb][j] = h;
            (bb ? hout1 : hout0)[t * NH + j] = h;
        }
        __syncthreads();
    }
}

// ---------------------------------------------------------------------------
// Kernel 3: emissions = concat(h_f[b,t], h_b[b,rev(b,t)]) @ w_out^T + b_out
// One block per (b,t); 128 threads = 32 tags x 4 partial sums.
// ---------------------------------------------------------------------------
__global__ void __launch_bounds__(128) emissions_kernel(
    const int* __restrict__ lens, const float* __restrict__ w_out,
    const float* __restrict__ b_out)
{
    const int m = blockIdx.x;
    const int b = m >> 8, t = m & 255;
    const int tid = threadIdx.x;
    const int c = tid >> 2, part = tid & 3;
    const int len = lens[b];
    const int tb = (t < len) ? (len - 1 - t) : t;

    const int koff = part * 128;
    const float* hsrc;
    if (part < 2)
        hsrc = g_h + ((size_t)0 * NB + b) * NT * NH + (size_t)t * NH + koff;
    else
        hsrc = g_h + ((size_t)1 * NB + b) * NT * NH + (size_t)tb * NH + (koff - 256);

    const float4* h4 = (const float4*)hsrc;
    const float4* w4 = (const float4*)(w_out + (size_t)c * (2 * NH) + koff);
    float s = 0.0f;
#pragma unroll
    for (int k = 0; k < 32; ++k) {
        float4 hh = h4[k], ww = w4[k];
        s += hh.x * ww.x + hh.y * ww.y + hh.z * ww.z + hh.w * ww.w;
    }
    s += __shfl_xor_sync(0xffffffffu, s, 1);
    s += __shfl_xor_sync(0xffffffffu, s, 2);
    if (part == 0) g_em[((size_t)b * NT + t) * NC + c] = s + b_out[c];
}

// ---------------------------------------------------------------------------
// Kernel 4: Viterbi decode. One warp per batch element; lane = tag.
// Matches reference masking: score frozen for t >= len; hist recorded always;
// backtrack only for t < len-1; argmax = first max (strict >, min-index ties).
// Output: d_out[0 .. B*T) = paths (as float), d_out[B*T .. B*T+B) = best_score.
// ---------------------------------------------------------------------------
__global__ void __launch_bounds__(32) viterbi_kernel(
    const int* __restrict__ lens,
    const float* __restrict__ start_trans, const float* __restrict__ end_trans,
    const float* __restrict__ trans, float* __restrict__ out)
{
    const int b = blockIdx.x;
    const int lane = threadIdx.x;

    __shared__ float transT[NC][NC + 1];  // transT[c_cur][c_prev], padded
    for (int idx = lane; idx < NC * NC; idx += 32) {
        int cp = idx >> 5, cc = idx & 31;
        transT[cc][cp] = trans[idx];
    }
    __syncwarp();

    const int len = lens[b];
    float score = start_trans[lane] + g_em[((size_t)b * NT) * NC + lane];

    for (int t = 1; t < NT; ++t) {
        float best = -1e30f;
        int bp = 0;
#pragma unroll
        for (int cp = 0; cp < NC; ++cp) {
            float sc = __shfl_sync(0xffffffffu, score, cp) + transT[lane][cp];
            if (sc > best) { best = sc; bp = cp; }
        }
        g_hist[((size_t)(t - 1) * NB + b) * NC + lane] = bp;
        if (t < len) score = best + g_em[((size_t)b * NT + t) * NC + lane];
    }
    score += end_trans[lane];

    // warp argmax, first-max semantics (ties -> smaller index)
    float v = score;
    int idx = lane;
#pragma unroll
    for (int off = 16; off; off >>= 1) {
        float v2 = __shfl_xor_sync(0xffffffffu, v, off);
        int i2 = __shfl_xor_sync(0xffffffffu, idx, off);
        if (v2 > v || (v2 == v && i2 < idx)) { v = v2; idx = i2; }
    }

    if (lane == 0) {
        out[NB * NT + b] = v;
        int tag = idx;
        out[(size_t)b * NT + (NT - 1)] = (float)tag;
        for (int t = NT - 2; t >= 0; --t) {
            if (t < len - 1) tag = g_hist[((size_t)t * NB + b) * NC + tag];
            out[(size_t)b * NT + t] = (float)tag;
        }
    }
}

// ---------------------------------------------------------------------------
extern "C" void kernel_launch(void* const* d_in, const int* in_sizes, int n_in,
                              void* d_out, int out_size)
{
    const int*   sent   = (const int*)d_in[0];
    const int*   lens   = (const int*)d_in[1];
    const float* emb    = (const float*)d_in[2];
    const float* w_ih_f = (const float*)d_in[3];
    const float* w_hh_f = (const float*)d_in[4];
    const float* b_ih_f = (const float*)d_in[5];
    const float* b_hh_f = (const float*)d_in[6];
    const float* w_ih_b = (const float*)d_in[7];
    const float* w_hh_b = (const float*)d_in[8];
    const float* b_ih_b = (const float*)d_in[9];
    const float* b_hh_b = (const float*)d_in[10];
    const float* w_out  = (const float*)d_in[11];
    const float* b_out  = (const float*)d_in[12];
    const float* start_trans = (const float*)d_in[13];
    const float* end_trans   = (const float*)d_in[14];
    const float* trans       = (const float*)d_in[15];
    float* out = (float*)d_out;

    dim3 g1(128, 16);  // M tiles x (2 dirs * 8 N tiles)
    input_proj_kernel<<<g1, 256>>>(sent, lens, emb,
                                   w_ih_f, b_ih_f, b_hh_f,
                                   w_ih_b, b_ih_b, b_hh_b);
    lstm_kernel<<<64, 1024>>>(w_hh_f, w_hh_b);
    emissions_kernel<<<NB * NT, 128>>>(lens, w_out, b_out);
    viterbi_kernel<<<NB, 32>>>(lens, start_trans, end_trans, trans, out);
}

// round 4
// speedup vs baseline: 4.0238x; 4.0238x over previous
#include <cuda_runtime.h>
#include <math.h>

// Problem constants
constexpr int NB = 64;    // batch
constexpr int NT = 256;   // time
constexpr int ND = 256;   // embed dim
constexpr int NH = 256;   // hidden per direction
constexpr int NC = 32;    // tags
constexpr int NG = 1024;  // 4*NH gate rows

// Scratch (static device allocations; no cudaMalloc allowed)
__device__ __align__(16) float g_gates[(size_t)2 * NB * NT * NG]; // input-projected gate preacts per dir
__device__ __align__(16) float g_h[(size_t)2 * NB * NT * NH];     // LSTM outputs per dir (bwd in reversed time)
__device__ __align__(16) float g_em[(size_t)NB * NT * NC];        // emissions
__device__ __align__(16) float g_wT[(size_t)2 * NH * NG];         // w_hh transposed: [dir][k][g]
__device__ __align__(16) float g_wOutT[(size_t)2 * NH * NC];      // w_out transposed: [k][c]

__device__ __forceinline__ float sigf(float x) { return 1.0f / (1.0f + __expf(-x)); }

// ---------------------------------------------------------------------------
// Kernel 0a: transpose w_hh (both dirs) into g_wT[dir][k][g]
// ---------------------------------------------------------------------------
__global__ void transpose_whh_kernel(const float* __restrict__ wf,
                                     const float* __restrict__ wb)
{
    __shared__ float tile[32][33];
    const int z = blockIdx.z;
    const float* __restrict__ src = z ? wb : wf;
    float* dst = g_wT + (size_t)z * NH * NG;
    const int g0 = blockIdx.x * 32, k0 = blockIdx.y * 32;
    const int tx = threadIdx.x, ty = threadIdx.y;
#pragma unroll
    for (int i = 0; i < 32; i += 8)
        tile[ty + i][tx] = src[(size_t)(g0 + ty + i) * NH + k0 + tx];
    __syncthreads();
#pragma unroll
    for (int i = 0; i < 32; i += 8)
        dst[(size_t)(k0 + ty + i) * NG + g0 + tx] = tile[tx][ty + i];
}

// ---------------------------------------------------------------------------
// Kernel 0b: transpose w_out [32][512] -> g_wOutT[512][32]
// ---------------------------------------------------------------------------
__global__ void transpose_wout_kernel(const float* __restrict__ w)
{
    __shared__ float tile[32][33];
    const int k0 = blockIdx.x * 32;
    const int tx = threadIdx.x, ty = threadIdx.y;
#pragma unroll
    for (int i = 0; i < 32; i += 8)
        tile[ty + i][tx] = w[(size_t)(ty + i) * (2 * NH) + k0 + tx];
    __syncthreads();
#pragma unroll
    for (int i = 0; i < 32; i += 8)
        g_wOutT[(size_t)(k0 + ty + i) * NC + tx] = tile[tx][ty + i];
}

// ---------------------------------------------------------------------------
// Kernel 1: embedding gather + input projection for both directions.
// gates[dir][b][t][g] = dot(emb[token(dir,b,t)], w_ih[g,:]) + b_ih[g] + b_hh[g]
// SGEMM: BM=128, BN=128, BK=16, 256 threads, 8x8 per-thread microtile.
// ---------------------------------------------------------------------------
__global__ void __launch_bounds__(256) input_proj_kernel(
    const int* __restrict__ sent, const int* __restrict__ lens,
    const float* __restrict__ emb,
    const float* __restrict__ w_f, const float* __restrict__ bi_f, const float* __restrict__ bh_f,
    const float* __restrict__ w_b, const float* __restrict__ bi_b, const float* __restrict__ bh_b)
{
    const int dir = blockIdx.y >> 3;
    const int n0  = (blockIdx.y & 7) * 128;
    const int m0  = blockIdx.x * 128;

    const float* __restrict__ W  = dir ? w_b  : w_f;
    const float* __restrict__ BI = dir ? bi_b : bi_f;
    const float* __restrict__ BH = dir ? bh_b : bh_f;

    __shared__ __align__(16) float As[16][128];
    __shared__ __align__(16) float Bs[16][128];
    __shared__ int toks[128];

    const int tid = threadIdx.x;
    if (tid < 128) {
        int m = m0 + tid;
        int b = m >> 8, t = m & 255;
        int ts = t;
        if (dir) { int len = lens[b]; if (t < len) ts = len - 1 - t; }
        toks[tid] = sent[b * NT + ts];
    }
    __syncthreads();

    // Staging mapping: 4 lanes per row, 8 rows per warp -> nL=8 per LDG.128
    const int lrow2 = tid >> 2;   // 0..63
    const int lane4 = tid & 3;    // 0..3
    const int row0 = lrow2, row1 = lrow2 + 64;
    const float* arow0 = emb + (size_t)toks[row0] * ND + lane4 * 4;
    const float* arow1 = emb + (size_t)toks[row1] * ND + lane4 * 4;
    const float* brow0 = W + (size_t)(n0 + row0) * ND + lane4 * 4;
    const float* brow1 = W + (size_t)(n0 + row1) * ND + lane4 * 4;

    const int tx = tid & 15, ty = tid >> 4;

    float acc[8][8];
#pragma unroll
    for (int i = 0; i < 8; i++)
#pragma unroll
        for (int j = 0; j < 8; j++) acc[i][j] = 0.0f;

    for (int kk = 0; kk < ND; kk += 16) {
        float4 a0 = *(const float4*)(arow0 + kk);
        float4 a1 = *(const float4*)(arow1 + kk);
        float4 b0 = *(const float4*)(brow0 + kk);
        float4 b1 = *(const float4*)(brow1 + kk);
        As[lane4 * 4 + 0][row0] = a0.x; As[lane4 * 4 + 1][row0] = a0.y;
        As[lane4 * 4 + 2][row0] = a0.z; As[lane4 * 4 + 3][row0] = a0.w;
        As[lane4 * 4 + 0][row1] = a1.x; As[lane4 * 4 + 1][row1] = a1.y;
        As[lane4 * 4 + 2][row1] = a1.z; As[lane4 * 4 + 3][row1] = a1.w;
        Bs[lane4 * 4 + 0][row0] = b0.x; Bs[lane4 * 4 + 1][row0] = b0.y;
        Bs[lane4 * 4 + 2][row0] = b0.z; Bs[lane4 * 4 + 3][row0] = b0.w;
        Bs[lane4 * 4 + 0][row1] = b1.x; Bs[lane4 * 4 + 1][row1] = b1.y;
        Bs[lane4 * 4 + 2][row1] = b1.z; Bs[lane4 * 4 + 3][row1] = b1.w;
        __syncthreads();
#pragma unroll
        for (int k = 0; k < 16; ++k) {
            float4 av0 = *(const float4*)&As[k][ty * 8];
            float4 av1 = *(const float4*)&As[k][ty * 8 + 4];
            float4 bv0 = *(const float4*)&Bs[k][tx * 8];
            float4 bv1 = *(const float4*)&Bs[k][tx * 8 + 4];
            float a[8] = {av0.x, av0.y, av0.z, av0.w, av1.x, av1.y, av1.z, av1.w};
            float bb[8] = {bv0.x, bv0.y, bv0.z, bv0.w, bv1.x, bv1.y, bv1.z, bv1.w};
#pragma unroll
            for (int i = 0; i < 8; i++)
#pragma unroll
                for (int j = 0; j < 8; j++) acc[i][j] = fmaf(a[i], bb[j], acc[i][j]);
        }
        __syncthreads();
    }

    float bias[8];
#pragma unroll
    for (int j = 0; j < 8; j++) {
        int n = n0 + tx * 8 + j;
        bias[j] = BI[n] + BH[n];
    }
#pragma unroll
    for (int i = 0; i < 8; i++) {
        int m = m0 + ty * 8 + i;
        float* o = g_gates + ((size_t)dir * (NB * NT) + m) * NG + n0 + tx * 8;
        float4 s0, s1;
        s0.x = acc[i][0] + bias[0]; s0.y = acc[i][1] + bias[1];
        s0.z = acc[i][2] + bias[2]; s0.w = acc[i][3] + bias[3];
        s1.x = acc[i][4] + bias[4]; s1.y = acc[i][5] + bias[5];
        s1.z = acc[i][6] + bias[6]; s1.w = acc[i][7] + bias[7];
        *(float4*)o = s0;
        *(float4*)(o + 4) = s1;
    }
}

// ---------------------------------------------------------------------------
// Kernel 2: recurrent LSTM with transposed weights (coalesced loads).
// 64 blocks: blockIdx&1 = dir, blockIdx>>1 = batch pair.
// 512 threads: thread owns gate rows {2*tid, 2*tid+1} for both batches.
// Weight loads: wT[k][2*tid..2*tid+1] -> lane-consecutive LDG.64 (nL=2).
// Cell state kept in registers of the activation thread.
// ---------------------------------------------------------------------------
__global__ void __launch_bounds__(512, 1) lstm_kernel()
{
    const int dir = blockIdx.x & 1;
    const int b0 = (blockIdx.x >> 1) * 2;
    const float* __restrict__ W = g_wT + (size_t)dir * NH * NG;
    const float2* __restrict__ Wv = (const float2*)W;  // index k*512 + tid

    __shared__ __align__(16) float hs[2][NH];
    __shared__ __align__(16) float gs[2][NG];

    const int tid = threadIdx.x;
    const int bb = tid >> 8, j = tid & 255;  // activation mapping (all 512 threads)
    float c_reg = 0.0f;
    hs[bb][j] = 0.0f;
    __syncthreads();

    const float* gin0 = g_gates + ((size_t)dir * NB + b0) * NT * NG;
    const float* gin1 = gin0 + (size_t)NT * NG;
    float* hout0 = g_h + ((size_t)dir * NB + b0) * NT * NH;
    float* hout1 = hout0 + (size_t)NT * NH;
    const float4* h0v = (const float4*)hs[0];
    const float4* h1v = (const float4*)hs[1];

    const int g2 = 2 * tid;

    for (int t = 0; t < NT; ++t) {
        float2 gv0 = *(const float2*)(gin0 + (size_t)t * NG + g2);
        float2 gv1 = *(const float2*)(gin1 + (size_t)t * NG + g2);
        float acc00 = gv0.x, acc01 = gv0.y;  // batch0, rows g2, g2+1
        float acc10 = gv1.x, acc11 = gv1.y;  // batch1
        if (t > 0) {
#pragma unroll 4
            for (int k4 = 0; k4 < NH / 4; ++k4) {
                float4 h0 = h0v[k4];
                float4 h1 = h1v[k4];
                float2 w0 = Wv[(k4 * 4 + 0) * 512 + tid];
                float2 w1 = Wv[(k4 * 4 + 1) * 512 + tid];
                float2 w2 = Wv[(k4 * 4 + 2) * 512 + tid];
                float2 w3 = Wv[(k4 * 4 + 3) * 512 + tid];
                acc00 = fmaf(w0.x, h0.x, acc00); acc01 = fmaf(w0.y, h0.x, acc01);
                acc10 = fmaf(w0.x, h1.x, acc10); acc11 = fmaf(w0.y, h1.x, acc11);
                acc00 = fmaf(w1.x, h0.y, acc00); acc01 = fmaf(w1.y, h0.y, acc01);
                acc10 = fmaf(w1.x, h1.y, acc10); acc11 = fmaf(w1.y, h1.y, acc11);
                acc00 = fmaf(w2.x, h0.z, acc00); acc01 = fmaf(w2.y, h0.z, acc01);
                acc10 = fmaf(w2.x, h1.z, acc10); acc11 = fmaf(w2.y, h1.z, acc11);
                acc00 = fmaf(w3.x, h0.w, acc00); acc01 = fmaf(w3.y, h0.w, acc01);
                acc10 = fmaf(w3.x, h1.w, acc10); acc11 = fmaf(w3.y, h1.w, acc11);
            }
        }
        *(float2*)&gs[0][g2] = make_float2(acc00, acc01);
        *(float2*)&gs[1][g2] = make_float2(acc10, acc11);
        __syncthreads();
        {
            float iv = sigf(gs[bb][j]);
            float fv = sigf(gs[bb][256 + j]);
            float gv = tanhf(gs[bb][512 + j]);
            float ov = sigf(gs[bb][768 + j]);
            c_reg = fv * c_reg + iv * gv;
            float h = ov * tanhf(c_reg);
            hs[bb][j] = h;
            (bb ? hout1 : hout0)[(size_t)t * NH + j] = h;
        }
        __syncthreads();
    }
}

// ---------------------------------------------------------------------------
// Kernel 3: emissions. One warp per (b,t); lane = tag.
// wOutT reads are lane-coalesced (128B/line); h reads are uniform broadcasts.
// ---------------------------------------------------------------------------
__global__ void __launch_bounds__(256) emissions_kernel(
    const int* __restrict__ lens, const float* __restrict__ b_out)
{
    const int item = blockIdx.x * 8 + (threadIdx.x >> 5);
    const int lane = threadIdx.x & 31;
    const int b = item >> 8, t = item & 255;
    const int len = lens[b];
    const int tb = (t < len) ? (len - 1 - t) : t;

    const float* hf = g_h + ((size_t)0 * NB + b) * NT * NH + (size_t)t * NH;
    const float* hb = g_h + ((size_t)1 * NB + b) * NT * NH + (size_t)tb * NH;
    const float* __restrict__ wT = g_wOutT;

    float acc = b_out[lane];
#pragma unroll 4
    for (int k4 = 0; k4 < 64; ++k4) {
        float4 h = *(const float4*)(hf + k4 * 4);
        acc = fmaf(h.x, wT[(k4 * 4 + 0) * NC + lane], acc);
        acc = fmaf(h.y, wT[(k4 * 4 + 1) * NC + lane], acc);
        acc = fmaf(h.z, wT[(k4 * 4 + 2) * NC + lane], acc);
        acc = fmaf(h.w, wT[(k4 * 4 + 3) * NC + lane], acc);
    }
#pragma unroll 4
    for (int k4 = 0; k4 < 64; ++k4) {
        float4 h = *(const float4*)(hb + k4 * 4);
        acc = fmaf(h.x, wT[(NH + k4 * 4 + 0) * NC + lane], acc);
        acc = fmaf(h.y, wT[(NH + k4 * 4 + 1) * NC + lane], acc);
        acc = fmaf(h.z, wT[(NH + k4 * 4 + 2) * NC + lane], acc);
        acc = fmaf(h.w, wT[(NH + k4 * 4 + 3) * NC + lane], acc);
    }
    g_em[(size_t)item * NC + lane] = acc;
}

// ---------------------------------------------------------------------------
// Kernel 4: Viterbi decode. One block (1 warp) per batch element; lane = tag.
// Transitions in registers; emissions prefetched; backpointers in SMEM.
// argmax = first-max (strict >, min-index ties) to match jnp.argmax.
// Output: out[0 .. B*T) = paths (float), out[B*T .. B*T+B) = best_score.
// ---------------------------------------------------------------------------
__global__ void __launch_bounds__(32) viterbi_kernel(
    const int* __restrict__ lens,
    const float* __restrict__ start_trans, const float* __restrict__ end_trans,
    const float* __restrict__ trans, float* __restrict__ out)
{
    const int b = blockIdx.x;
    const int lane = threadIdx.x;

    __shared__ int hist[NT - 1][NC];

    float tr[NC];  // tr[cp] = trans[cp][lane]
#pragma unroll
    for (int cp = 0; cp < NC; ++cp) tr[cp] = trans[cp * NC + lane];

    const int len = lens[b];
    const float* emp = g_em + (size_t)b * NT * NC;
    float score = start_trans[lane] + emp[lane];
    float em_next = emp[NC + lane];

    for (int t = 1; t < NT; ++t) {
        float best = -1e30f;
        int bp = 0;
#pragma unroll
        for (int cp = 0; cp < NC; ++cp) {
            float sc = __shfl_sync(0xffffffffu, score, cp) + tr[cp];
            if (sc > best) { best = sc; bp = cp; }
        }
        hist[t - 1][lane] = bp;
        float em_cur = em_next;
        if (t + 1 < NT) em_next = emp[(t + 1) * NC + lane];
        if (t < len) score = best + em_cur;
    }
    score += end_trans[lane];

    // warp argmax, first-max semantics
    float v = score;
    int idx = lane;
#pragma unroll
    for (int off = 16; off; off >>= 1) {
        float v2 = __shfl_xor_sync(0xffffffffu, v, off);
        int i2 = __shfl_xor_sync(0xffffffffu, idx, off);
        if (v2 > v || (v2 == v && i2 < idx)) { v = v2; idx = i2; }
    }

    if (lane == 0) {
        out[NB * NT + b] = v;
        int tag = idx;
        out[(size_t)b * NT + (NT - 1)] = (float)tag;
        for (int t = NT - 2; t >= 0; --t) {
            if (t < len - 1) tag = hist[t][tag];
            out[(size_t)b * NT + t] = (float)tag;
        }
    }
}

// ---------------------------------------------------------------------------
extern "C" void kernel_launch(void* const* d_in, const int* in_sizes, int n_in,
                              void* d_out, int out_size)
{
    const int*   sent   = (const int*)d_in[0];
    const int*   lens   = (const int*)d_in[1];
    const float* emb    = (const float*)d_in[2];
    const float* w_ih_f = (const float*)d_in[3];
    const float* w_hh_f = (const float*)d_in[4];
    const float* b_ih_f = (const float*)d_in[5];
    const float* b_hh_f = (const float*)d_in[6];
    const float* w_ih_b = (const float*)d_in[7];
    const float* w_hh_b = (const float*)d_in[8];
    const float* b_ih_b = (const float*)d_in[9];
    const float* b_hh_b = (const float*)d_in[10];
    const float* w_out  = (const float*)d_in[11];
    const float* b_out  = (const float*)d_in[12];
    const float* start_trans = (const float*)d_in[13];
    const float* end_trans   = (const float*)d_in[14];
    const float* trans       = (const float*)d_in[15];
    float* out = (float*)d_out;

    dim3 tb(32, 8);
    transpose_whh_kernel<<<dim3(NG / 32, NH / 32, 2), tb>>>(w_hh_f, w_hh_b);
    transpose_wout_kernel<<<dim3((2 * NH) / 32, 1, 1), tb>>>(w_out);

    dim3 g1(128, 16);  // M tiles x (2 dirs * 8 N tiles)
    input_proj_kernel<<<g1, 256>>>(sent, lens, emb,
                                   w_ih_f, b_ih_f, b_hh_f,
                                   w_ih_b, b_ih_b, b_hh_b);
    lstm_kernel<<<64, 512>>>();
    emissions_kernel<<<NB * NT / 8, 256>>>(lens, b_out);
    viterbi_kernel<<<NB, 32>>>(lens, start_trans, end_trans, trans, out);
}